// round 1
// baseline (speedup 1.0000x reference)
#include <cuda_runtime.h>

// Problem constants
#define HH 8
#define NN 2048
#define ROWS (HH * NN)              // 16384
#define GAMMA 0.9f
#define TOL2 1e-12f                  // (1e-6)^2
#define MAX_ITER 50

// Launch shape: persistent kernel, all blocks co-resident (GB300 has 152 SMs)
#define NBLOCKS 148
#define NTHREADS 1024
#define NWARPS (NTHREADS / 32)
#define TOTAL_WARPS (NBLOCKS * NWARPS)   // 4736

// Device-global scratch (no allocation allowed)
__device__ float    g_x[2][ROWS];        // ping-pong fixed-point iterate
__device__ float    g_bsum[2][NBLOCKS];  // per-block partial ||x - x_next||^2 (parity ping-pong)
__device__ unsigned g_arrive = 0;        // grid barrier arrival counter
__device__ unsigned g_gen    = 0;        // grid barrier generation (monotonic across replays)

// Software grid barrier: safe because all NBLOCKS blocks are co-resident.
__device__ __forceinline__ void grid_barrier() {
    __syncthreads();
    if (threadIdx.x == 0) {
        volatile unsigned* genp = &g_gen;
        unsigned my = *genp;             // read generation BEFORE arriving
        __threadfence();                 // make this block's prior writes visible
        unsigned prev = atomicAdd(&g_arrive, 1u);
        if (prev == NBLOCKS - 1) {
            atomicExch(&g_arrive, 0u);
            __threadfence();
            atomicAdd(&g_gen, 1u);       // release everyone
        } else {
            while (*genp == my) { }      // spin on L2-coherent volatile load
        }
        __threadfence();                 // acquire: see all other blocks' writes
    }
    __syncthreads();
}

extern __shared__ float s_dyn[];         // [ROWS] current x  +  [NWARPS] reduce scratch

__global__ void __launch_bounds__(NTHREADS, 1)
fp_kernel(const float* __restrict__ A, const float* __restrict__ b,
          float* __restrict__ out)
{
    float* xs  = s_dyn;                  // 16384 floats = current iterate x (all heads)
    float* red = s_dyn + ROWS;           // per-warp diff^2 partials
    __shared__ float parts[256];         // deterministic cross-block reduction scratch

    const int tid  = threadIdx.x;
    const int warp = tid >> 5;
    const int lane = tid & 31;
    const int gw   = blockIdx.x * NWARPS + warp;   // global warp id

    // x0 = 0 (zero the smem copy; iteration 0 reads it)
    {
        float4 z4 = make_float4(0.f, 0.f, 0.f, 0.f);
        float4* xs4 = reinterpret_cast<float4*>(xs);
        for (int i = tid; i < ROWS / 4; i += NTHREADS) xs4[i] = z4;
    }
    __syncthreads();

    int finalbuf = 0;

    for (int iter = 0; iter <= MAX_ITER; ++iter) {
        const int par = iter & 1;
        float* __restrict__ xw = g_x[par];   // write buffer for x_{iter+1}

        // ---- batched matvec: one row per warp, strided over all 16384 rows ----
        float lsum = 0.f;                    // lane 0 accumulates (x - x_next)^2
        for (int row = gw; row < ROWS; row += TOTAL_WARPS) {
            const int h = row >> 11;         // head index
            const float4* __restrict__ a4 =
                reinterpret_cast<const float4*>(A + (size_t)row * NN);
            const float4* __restrict__ x4 =
                reinterpret_cast<const float4*>(xs + h * NN);

            float acc0 = 0.f, acc1 = 0.f;
            #pragma unroll
            for (int k = 0; k < 16; k += 2) {
                float4 a  = a4[lane + 32 * k];
                float4 xv = x4[lane + 32 * k];
                acc0 = fmaf(a.x, xv.x, acc0);
                acc0 = fmaf(a.y, xv.y, acc0);
                acc0 = fmaf(a.z, xv.z, acc0);
                acc0 = fmaf(a.w, xv.w, acc0);
                float4 a2  = a4[lane + 32 * (k + 1)];
                float4 xv2 = x4[lane + 32 * (k + 1)];
                acc1 = fmaf(a2.x, xv2.x, acc1);
                acc1 = fmaf(a2.y, xv2.y, acc1);
                acc1 = fmaf(a2.z, xv2.z, acc1);
                acc1 = fmaf(a2.w, xv2.w, acc1);
            }
            float acc = acc0 + acc1;
            #pragma unroll
            for (int o = 16; o > 0; o >>= 1)
                acc += __shfl_xor_sync(0xFFFFFFFFu, acc, o);

            if (lane == 0) {
                float y = tanhf(GAMMA * acc + b[row]);
                xw[row] = y;
                float d = xs[row] - y;
                lsum = fmaf(d, d, lsum);
            }
        }

        // ---- block-level diff^2 reduction (deterministic order) ----
        if (lane == 0) red[warp] = lsum;
        __syncthreads();
        if (warp == 0) {
            float s = (lane < NWARPS) ? red[lane] : 0.f;
            #pragma unroll
            for (int o = 16; o > 0; o >>= 1)
                s += __shfl_xor_sync(0xFFFFFFFFu, s, o);
            if (lane == 0) g_bsum[par][blockIdx.x] = s;
        }

        grid_barrier();   // all x_{iter+1} writes + block sums now globally visible

        // ---- deterministic cross-block reduction (every block computes the
        //      identical sum in identical order -> identical decision) ----
        parts[tid & 255] = 0.f;   // only first 256 threads matter; all write once
        __syncthreads();
        if (tid < 256) parts[tid] = (tid < NBLOCKS) ? g_bsum[par][tid] : 0.f;
        __syncthreads();
        #pragma unroll
        for (int s = 128; s > 0; s >>= 1) {
            if (tid < s) parts[tid] += parts[tid + s];
            __syncthreads();
        }
        float sumsq = parts[0];
        __syncthreads();          // everyone done reading parts before next iter reuses it

        if (sumsq < TOL2 || iter == MAX_ITER) {
            // Converged at this step: output is exactly x_next = tanh(g*A@z_star + b),
            // which is what we just wrote. (iter==MAX_ITER is the extra diff. step.)
            finalbuf = par;
            break;
        }

        // Reload the new iterate into shared memory for the next pass.
        {
            const float4* src = reinterpret_cast<const float4*>(g_x[par]);
            float4* dst = reinterpret_cast<float4*>(xs);
            for (int i = tid; i < ROWS / 4; i += NTHREADS) dst[i] = src[i];
        }
        __syncthreads();
    }

    // ---- copy final buffer to d_out (shape [8,2048] row-major == x layout) ----
    {
        const float4* src = reinterpret_cast<const float4*>(g_x[finalbuf]);
        float4* dst = reinterpret_cast<float4*>(out);
        for (int i = blockIdx.x * NTHREADS + tid; i < ROWS / 4; i += NBLOCKS * NTHREADS)
            dst[i] = src[i];
    }
}

extern "C" void kernel_launch(void* const* d_in, const int* in_sizes, int n_in,
                              void* d_out, int out_size)
{
    const float* A = (const float*)d_in[0];
    const float* b = (const float*)d_in[1];
    // Defensive: identify A by element count (A has 33.5M elems, b has 16384)
    if (n_in >= 2 && in_sizes[0] == ROWS) {
        A = (const float*)d_in[1];
        b = (const float*)d_in[0];
    }

    size_t smem = (size_t)ROWS * sizeof(float) + (size_t)NWARPS * sizeof(float);
    cudaFuncSetAttribute(fp_kernel, cudaFuncAttributeMaxDynamicSharedMemorySize,
                         (int)smem);
    fp_kernel<<<NBLOCKS, NTHREADS, smem>>>(A, b, (float*)d_out);
}